// round 5
// baseline (speedup 1.0000x reference)
#include <cuda_runtime.h>
#include <cstdint>

#define N_NODES 100000
#define D 64
#define VEC_PER_ROW (D / 4)      // 16 float4 per node row
#define N_EDGES 1600000

#define SCAN_CHUNK 512
#define N_SCAN_BLOCKS ((N_NODES + SCAN_CHUNK - 1) / SCAN_CHUNK)   // 196

// Static scratch (allocation-free rule). g_counts is zero at module load and
// re-zeroed by aggregate_kernel at the end of every launch sequence.
__device__ int g_counts[N_NODES];      // in-degree (excluding self-loop)
__device__ int g_row_start[N_NODES];   // CSR offsets
__device__ int g_cursor[N_NODES];      // fill cursors
__device__ int g_block_sums[N_SCAN_BLOCKS];
__device__ int g_csr_src[N_EDGES];     // src ids grouped by dst

// ---------------------------------------------------------------- CSR build

// Histogram destinations. int4-vectorized edge reads (N_EDGES % 4 == 0).
__global__ void count_kernel(const int* __restrict__ ei) {
    int i = blockIdx.x * blockDim.x + threadIdx.x;
    if (i < N_EDGES / 4) {
        int4 d = ((const int4*)(ei + N_EDGES))[i];
        atomicAdd(&g_counts[d.x], 1);
        atomicAdd(&g_counts[d.y], 1);
        atomicAdd(&g_counts[d.z], 1);
        atomicAdd(&g_counts[d.w], 1);
    }
}

// Per-chunk sums (512 elements per block).
__global__ void scan1_kernel() {
    __shared__ int sdata[SCAN_CHUNK];
    int tid = threadIdx.x;
    int i = blockIdx.x * SCAN_CHUNK + tid;
    sdata[tid] = (i < N_NODES) ? g_counts[i] : 0;
    __syncthreads();
    for (int s = SCAN_CHUNK / 2; s > 0; s >>= 1) {
        if (tid < s) sdata[tid] += sdata[tid + s];
        __syncthreads();
    }
    if (tid == 0) g_block_sums[blockIdx.x] = sdata[0];
}

// Fused: every block (redundantly) scans the 196 chunk sums in shared to get
// its own offset, then does its in-chunk exclusive scan -> row_start, cursor.
__global__ void scan23_kernel() {
    __shared__ int ssum[256];
    __shared__ int sdata[SCAN_CHUNK];
    int tid = threadIdx.x;

    if (tid < 256) ssum[tid] = (tid < N_SCAN_BLOCKS) ? g_block_sums[tid] : 0;
    __syncthreads();
    // Hillis-Steele inclusive scan over the 256-entry sum array.
    for (int off = 1; off < 256; off <<= 1) {
        int t = 0;
        if (tid < 256 && tid >= off) t = ssum[tid - off];
        __syncthreads();
        if (tid < 256) ssum[tid] += t;
        __syncthreads();
    }
    int block_off = (blockIdx.x == 0) ? 0 : ssum[blockIdx.x - 1];

    int i = blockIdx.x * SCAN_CHUNK + tid;
    int v = (i < N_NODES) ? g_counts[i] : 0;
    sdata[tid] = v;
    __syncthreads();
    // Hillis-Steele inclusive scan over the chunk.
    for (int off = 1; off < SCAN_CHUNK; off <<= 1) {
        int t = (tid >= off) ? sdata[tid - off] : 0;
        __syncthreads();
        sdata[tid] += t;
        __syncthreads();
    }
    if (i < N_NODES) {
        int excl = sdata[tid] - v + block_off;
        g_row_start[i] = excl;
        g_cursor[i] = excl;
    }
}

// Bucket src ids by destination. int4-vectorized edge reads.
__global__ void fill_kernel(const int* __restrict__ ei) {
    int i = blockIdx.x * blockDim.x + threadIdx.x;
    if (i < N_EDGES / 4) {
        int4 s = ((const int4*)ei)[i];
        int4 d = ((const int4*)(ei + N_EDGES))[i];
        g_csr_src[atomicAdd(&g_cursor[d.x], 1)] = s.x;
        g_csr_src[atomicAdd(&g_cursor[d.y], 1)] = s.y;
        g_csr_src[atomicAdd(&g_cursor[d.z], 1)] = s.z;
        g_csr_src[atomicAdd(&g_cursor[d.w], 1)] = s.w;
    }
}

// ---------------------------------------------------------------- aggregate
// One warp per destination node. Lane c<16 handles float4 chunk c of the real
// row; lane c>=16 handles chunk c-16 of the imag row. Accumulator starts with
// the node's own row (self-loop); final scale 1/(deg+1) gives the mean.
// Lane 0 re-zeroes g_counts[n] after use so the next replay starts clean.
__global__ void aggregate_kernel(const float* __restrict__ Zr,
                                 const float* __restrict__ Zi,
                                 float* __restrict__ out) {
    int warp_id = (blockIdx.x * blockDim.x + threadIdx.x) >> 5;
    int lane = threadIdx.x & 31;
    if (warp_id >= N_NODES) return;
    int n = warp_id;

    const float4* Zr4 = (const float4*)Zr;
    const float4* Zi4 = (const float4*)Zi;

    bool is_real = lane < 16;
    int chunk = is_real ? lane : lane - 16;

    // self-loop init
    float4 acc = is_real ? Zr4[(size_t)n * VEC_PER_ROW + chunk]
                         : Zi4[(size_t)n * VEC_PER_ROW + chunk];

    int start = g_row_start[n];
    int deg = g_counts[n];
    if (lane == 0) g_counts[n] = 0;   // reset for next graph replay

    // software-pipelined index to overlap index load with gather
    int s_next = (deg > 0) ? g_csr_src[start] : 0;
    for (int j = 0; j < deg; j++) {
        int s = s_next;
        if (j + 1 < deg) s_next = g_csr_src[start + j + 1];
        float4 v = is_real ? Zr4[(size_t)s * VEC_PER_ROW + chunk]
                           : Zi4[(size_t)s * VEC_PER_ROW + chunk];
        acc.x += v.x; acc.y += v.y; acc.z += v.z; acc.w += v.w;
    }

    float inv = 1.0f / (float)(deg + 1);
    acc.x *= inv; acc.y *= inv; acc.z *= inv; acc.w *= inv;

    float4* o = is_real ? (float4*)out : (float4*)(out + (size_t)N_NODES * D);
    o[(size_t)n * VEC_PER_ROW + chunk] = acc;
}

// ---------------------------------------------------------------- launch
extern "C" void kernel_launch(void* const* d_in, const int* in_sizes, int n_in,
                              void* d_out, int out_size) {
    const float* Zr = (const float*)d_in[0];
    const float* Zi = (const float*)d_in[1];
    const int* ei = (const int*)d_in[2];
    float* out = (float*)d_out;

    {
        int threads = 256;
        int blocks = (N_EDGES / 4 + threads - 1) / threads;
        count_kernel<<<blocks, threads>>>(ei);
    }
    scan1_kernel<<<N_SCAN_BLOCKS, SCAN_CHUNK>>>();
    scan23_kernel<<<N_SCAN_BLOCKS, SCAN_CHUNK>>>();
    {
        int threads = 256;
        int blocks = (N_EDGES / 4 + threads - 1) / threads;
        fill_kernel<<<blocks, threads>>>(ei);
    }
    {
        // one warp per node: 100000 warps, 8 warps (256 threads) per block
        int threads = 256;
        int blocks = (N_NODES * 32 + threads - 1) / threads;  // 12500
        aggregate_kernel<<<blocks, threads>>>(Zr, Zi, out);
    }
}